// round 1
// baseline (speedup 1.0000x reference)
#include <cuda_runtime.h>

#define NPTS 6000
#define NTRI 16000
#define NMOV 4000
#define NBND 1500
#define BB   16
#define KC   640          // K-chunk staged in smem: 640*16*4 = 40KB
#define EPSV 1e-8f

// ---------------- scratch (static __device__, no allocation) ----------------
__device__ float g_pz[BB * NPTS * 3];   // working point cloud, [b][p][xyz]
__device__ float g_D [NTRI * BB];       // per-triangle coefficients, [t][b]
__device__ float g_C [NMOV * BB];       // GEMM output, [m][b]
__device__ int   g_w1[NPTS];            // last writer in indices_1 per point (-1 none)
__device__ int   g_w2[NPTS];            // last writer in indices_2 per point
__device__ float g_vols[BB];
__device__ float g_volc;
__device__ float g_a  [BB];
__device__ float g_ssq[BB];

// ---------------- f32x2 packed-math helpers ----------------
__device__ __forceinline__ unsigned long long splat2(float f) {
    unsigned long long r;
    asm("mov.b64 %0, {%1, %1};" : "=l"(r) : "r"(__float_as_uint(f)));
    return r;
}
__device__ __forceinline__ unsigned long long fma2(unsigned long long a,
                                                   unsigned long long b,
                                                   unsigned long long c) {
    unsigned long long d;
    asm("fma.rn.f32x2 %0, %1, %2, %3;" : "=l"(d) : "l"(a), "l"(b), "l"(c));
    return d;
}
__device__ __forceinline__ float lo32(unsigned long long u) {
    return __int_as_float((int)(unsigned)(u & 0xffffffffull));
}
__device__ __forceinline__ float hi32(unsigned long long u) {
    return __int_as_float((int)(unsigned)(u >> 32));
}

// ---------------- setup kernels ----------------
__global__ void k_init() {
    int i = blockIdx.x * blockDim.x + threadIdx.x;
    if (i < NPTS) { g_w1[i] = -1; g_w2[i] = -1; }
    if (i < BB)   g_vols[i] = 0.f;
    if (i == 0)   g_volc = 0.f;
}

__global__ void k_winners(const int* __restrict__ idx1, const int* __restrict__ idx2) {
    int i = blockIdx.x * blockDim.x + threadIdx.x;
    if (i < NMOV) atomicMax(&g_w1[idx1[i]], i);
    if (i < NBND) atomicMax(&g_w2[idx2[i]], i);
}

__global__ void k_pz(const float* __restrict__ x, const float* __restrict__ y,
                     const float* __restrict__ p0) {
    int i = blockIdx.x * blockDim.x + threadIdx.x;
    if (i >= BB * NPTS) return;
    int b = i / NPTS, p = i - b * NPTS;
    float vx = p0[p * 3 + 0], vy = p0[p * 3 + 1], vz = p0[p * 3 + 2];
    int w2 = g_w2[p];
    if (w2 >= 0) {
        vx = y[b * 2 * NBND + 2 * w2 + 0];
        vz = y[b * 2 * NBND + 2 * w2 + 1];
    }
    int w1 = g_w1[p];
    if (w1 >= 0) {
        const float* xr = x + (size_t)(b * NMOV + w1) * 3;
        vx = xr[0]; vy = xr[1]; vz = xr[2];
    }
    float* o = g_pz + (size_t)(b * NPTS + p) * 3;
    o[0] = vx; o[1] = vy; o[2] = vz;
}

__global__ void k_copy(const float* __restrict__ x, float* __restrict__ out) {
    int i = blockIdx.x * blockDim.x + threadIdx.x;
    if (i < BB * NMOV * 3) out[i] = x[i];
}

__global__ void k_volc(const float* __restrict__ p0, const int* __restrict__ tri) {
    int t = blockIdx.x * blockDim.x + threadIdx.x;
    float term = 0.f;
    if (t < NTRI) {
        int i0 = tri[t * 3 + 0], i1 = tri[t * 3 + 1], i2 = tri[t * 3 + 2];
        float x0 = p0[i0 * 3], y0 = p0[i0 * 3 + 1], z0 = p0[i0 * 3 + 2];
        float x1 = p0[i1 * 3], y1 = p0[i1 * 3 + 1], z1 = p0[i1 * 3 + 2];
        float x2 = p0[i2 * 3], y2 = p0[i2 * 3 + 1], z2 = p0[i2 * 3 + 2];
        float d = ((y1 - y0) * (z2 - z0) - (z1 - z0) * (y2 - y0)) * (1.f / 6.f);
        term = (x0 + x1 + x2) * d;
    }
    #pragma unroll
    for (int off = 16; off; off >>= 1) term += __shfl_xor_sync(0xffffffffu, term, off);
    __shared__ float ws[8];
    int lane = threadIdx.x & 31, warp = threadIdx.x >> 5;
    if (lane == 0) ws[warp] = term;
    __syncthreads();
    if (threadIdx.x == 0) {
        float s = 0.f;
        #pragma unroll
        for (int w = 0; w < 8; w++) s += ws[w];
        atomicAdd(&g_volc, s);
    }
}

__global__ void k_vols(const int* __restrict__ tri) {
    __shared__ float sacc[BB];
    if (threadIdx.x < BB) sacc[threadIdx.x] = 0.f;
    __syncthreads();
    int i = blockIdx.x * blockDim.x + threadIdx.x;
    if (i < NTRI * BB) {
        int t = i >> 4, b = i & 15;
        int i0 = tri[t * 3 + 0], i1 = tri[t * 3 + 1], i2 = tri[t * 3 + 2];
        const float* P = g_pz + (size_t)b * NPTS * 3;
        float x0 = P[i0 * 3], y0 = P[i0 * 3 + 1], z0 = P[i0 * 3 + 2];
        float x1 = P[i1 * 3], y1 = P[i1 * 3 + 1], z1 = P[i1 * 3 + 2];
        float x2 = P[i2 * 3], y2 = P[i2 * 3 + 1], z2 = P[i2 * 3 + 2];
        float d = ((y1 - y0) * (z2 - z0) - (z1 - z0) * (y2 - y0)) * (1.f / 6.f);
        atomicAdd(&sacc[b], (x0 + x1 + x2) * d);
    }
    __syncthreads();
    if (threadIdx.x < BB) atomicAdd(&g_vols[threadIdx.x], sacc[threadIdx.x]);
}

__global__ void k_a() {
    int b = threadIdx.x;
    if (b < BB) g_a[b] = (g_volc - g_vols[b]) * (1.f / 3.f);
}

// ---------------- per-axis: triangle coefficients ----------------
__global__ void k_D(const int* __restrict__ tri, int axis) {
    int i = blockIdx.x * blockDim.x + threadIdx.x;
    if (blockIdx.x == 0 && threadIdx.x < BB) g_ssq[threadIdx.x] = 0.f;  // consumed by later launch
    if (i >= NTRI * BB) return;
    int t = i >> 4, b = i & 15;
    int i0 = tri[t * 3 + 0], i1 = tri[t * 3 + 1], i2 = tri[t * 3 + 2];
    const float* P = g_pz + (size_t)b * NPTS * 3;
    float d;
    if (axis == 2) {        // needs x,y: det([[x0-x2,y0-y2],[x1-x2,y1-y2]])/6
        float x0 = P[i0 * 3], y0 = P[i0 * 3 + 1];
        float x1 = P[i1 * 3], y1 = P[i1 * 3 + 1];
        float x2 = P[i2 * 3], y2 = P[i2 * 3 + 1];
        d = ((x0 - x2) * (y1 - y2) - (y0 - y2) * (x1 - x2)) * (1.f / 6.f);
    } else if (axis == 1) { // needs x,z: det([[x0-x1,z0-z1],[x2-x1,z2-z1]])/6
        float x0 = P[i0 * 3], z0 = P[i0 * 3 + 2];
        float x1 = P[i1 * 3], z1 = P[i1 * 3 + 2];
        float x2 = P[i2 * 3], z2 = P[i2 * 3 + 2];
        d = ((x0 - x1) * (z2 - z1) - (z0 - z1) * (x2 - x1)) * (1.f / 6.f);
    } else {                // needs y,z: det([[y1-y0,z1-z0],[y2-y0,z2-z0]])/6
        float y0 = P[i0 * 3 + 1], z0 = P[i0 * 3 + 2];
        float y1 = P[i1 * 3 + 1], z1 = P[i1 * 3 + 2];
        float y2 = P[i2 * 3 + 1], z2 = P[i2 * 3 + 2];
        d = ((y1 - y0) * (z2 - z0) - (z1 - z0) * (y2 - y0)) * (1.f / 6.f);
    }
    g_D[t * BB + b] = d;
}

// ---------------- the skinny GEMM: c[m][b] = sum_t Vf[m][t] * D[t][b] ----------------
// 256 threads = 8 warps; each warp owns 4 consecutive m-rows; lanes span t (coalesced
// float4 Vf loads). D staged in 40KB smem chunks; batches processed as 8 f32x2 pairs.
__global__ __launch_bounds__(256, 2) void k_gemm(const float* __restrict__ Vf) {
    __shared__ float Ds[KC * BB];
    int warp = threadIdx.x >> 5, lane = threadIdx.x & 31;
    int row0 = blockIdx.x * 32 + warp * 4;

    unsigned long long acc[4][8];
    #pragma unroll
    for (int r = 0; r < 4; r++)
        #pragma unroll
        for (int p = 0; p < 8; p++) acc[r][p] = 0ull;

    for (int k0 = 0; k0 < NTRI; k0 += KC) {
        __syncthreads();
        // stage D chunk (KC*16 floats) from L2 to smem
        const float4* src = (const float4*)(g_D + (size_t)k0 * BB);
        #pragma unroll
        for (int i = 0; i < (KC * BB / 4) / 256; i++) {
            int idx = threadIdx.x + i * 256;
            ((float4*)Ds)[idx] = src[idx];
        }
        __syncthreads();

        #pragma unroll
        for (int it = 0; it < KC / 128; ++it) {        // 5 macro-iters, 4 t's each
            int tloc = 4 * lane + 128 * it;
            float va[4][4];
            #pragma unroll
            for (int r = 0; r < 4; r++) {
                float4 v = *(const float4*)(Vf + (size_t)(row0 + r) * NTRI + k0 + tloc);
                va[r][0] = v.x; va[r][1] = v.y; va[r][2] = v.z; va[r][3] = v.w;
            }
            #pragma unroll
            for (int j = 0; j < 4; ++j) {
                const unsigned long long* dp =
                    (const unsigned long long*)(Ds + (tloc + j) * BB);
                unsigned long long dv[8];
                #pragma unroll
                for (int p = 0; p < 8; p++) dv[p] = dp[p];
                #pragma unroll
                for (int r = 0; r < 4; r++) {
                    unsigned long long s = splat2(va[r][j]);
                    #pragma unroll
                    for (int p = 0; p < 8; p++) acc[r][p] = fma2(s, dv[p], acc[r][p]);
                }
            }
        }
    }

    // reduce partial sums across the 32 t-lanes (f32 lanewise adds on unpacked halves)
    #pragma unroll
    for (int r = 0; r < 4; r++)
        #pragma unroll
        for (int p = 0; p < 8; p++) {
            float l = lo32(acc[r][p]), h = hi32(acc[r][p]);
            #pragma unroll
            for (int off = 16; off; off >>= 1) {
                l += __shfl_xor_sync(0xffffffffu, l, off);
                h += __shfl_xor_sync(0xffffffffu, h, off);
            }
            asm("mov.b64 %0, {%1, %2};" : "=l"(acc[r][p])
                : "r"(__float_as_uint(l)), "r"(__float_as_uint(h)));
        }

    if (lane == 0) {
        float sq[BB];
        #pragma unroll
        for (int b = 0; b < BB; b++) sq[b] = 0.f;
        #pragma unroll
        for (int r = 0; r < 4; r++) {
            unsigned long long* crow = (unsigned long long*)(g_C + (size_t)(row0 + r) * BB);
            #pragma unroll
            for (int p = 0; p < 8; p++) {
                crow[p] = acc[r][p];
                float l = lo32(acc[r][p]), h = hi32(acc[r][p]);
                sq[2 * p]     += l * l;
                sq[2 * p + 1] += h * h;
            }
        }
        #pragma unroll
        for (int b = 0; b < BB; b++) atomicAdd(&g_ssq[b], sq[b]);
    }
}

// ---------------- per-axis: solve + update pts + maintain pz ----------------
__global__ void k_update(const int* __restrict__ idx1, float* __restrict__ out, int axis) {
    int i = blockIdx.x * blockDim.x + threadIdx.x;
    if (i >= NMOV * BB) return;
    int m = i % NMOV, b = i / NMOV;
    float c = g_C[(size_t)m * BB + b];
    float s = g_a[b] / (g_ssq[b] + EPSV);
    size_t o = (size_t)(b * NMOV + m) * 3 + axis;
    float nv = out[o] + c * s;
    out[o] = nv;
    int p = idx1[m];
    if (g_w1[p] == m) g_pz[(size_t)(b * NPTS + p) * 3 + axis] = nv;
}

// ---------------- launch ----------------
extern "C" void kernel_launch(void* const* d_in, const int* in_sizes, int n_in,
                              void* d_out, int out_size) {
    const float* x   = (const float*)d_in[0];
    const float* y   = (const float*)d_in[1];
    const float* p0  = (const float*)d_in[2];
    const float* Vf  = (const float*)d_in[3];
    const int* idx1  = (const int*)d_in[4];
    const int* idx2  = (const int*)d_in[5];
    const int* tri   = (const int*)d_in[6];
    float* out       = (float*)d_out;

    k_init   <<<(NPTS + 255) / 256, 256>>>();
    k_winners<<<(NMOV + 255) / 256, 256>>>(idx1, idx2);
    k_pz     <<<(BB * NPTS + 255) / 256, 256>>>(x, y, p0);
    k_copy   <<<(BB * NMOV * 3 + 255) / 256, 256>>>(x, out);
    k_volc   <<<(NTRI + 255) / 256, 256>>>(p0, tri);
    k_vols   <<<(NTRI * BB + 255) / 256, 256>>>(tri);
    k_a      <<<1, 32>>>();

    const int axes[3] = {2, 1, 0};
    for (int ai = 0; ai < 3; ai++) {
        int axis = axes[ai];
        k_D     <<<(NTRI * BB + 255) / 256, 256>>>(tri, axis);
        k_gemm  <<<NMOV / 32, 256>>>(Vf);
        k_update<<<(NMOV * BB + 255) / 256, 256>>>(idx1, out, axis);
    }
}

// round 3
// speedup vs baseline: 2.0208x; 2.0208x over previous
#include <cuda_runtime.h>

#define NPTS 6000
#define NTRI 16000
#define NMOV 4000
#define NBND 1500
#define BB   16
#define KC   320          // K-chunk per smem buffer; 2 bufs * 8 planes * 320 * 8B = 40KB
#define NCHUNK (NTRI / KC)
#define GJ   5            // jj-group for Vf register prefetch
#define EPSV 1e-8f

// ---------------- scratch (static __device__, no allocation) ----------------
__device__ float g_pz[BB * NPTS * 3];                 // working point cloud [b][p][xyz]
__device__ unsigned long long g_Dp[8 * NTRI];         // D as 8 batch-pair planes [p][t] (float2)
__device__ float g_C [NMOV * BB];                     // GEMM output [m][b]
__device__ int   g_w1[NPTS];
__device__ int   g_w2[NPTS];
__device__ float g_vols[BB];
__device__ float g_volc;
__device__ float g_a  [BB];
__device__ float g_ssq[BB];

// ---------------- f32x2 packed-math helpers ----------------
__device__ __forceinline__ unsigned long long splat2(float f) {
    unsigned long long r;
    asm("mov.b64 %0, {%1, %1};" : "=l"(r) : "r"(__float_as_uint(f)));
    return r;
}
__device__ __forceinline__ unsigned long long fma2(unsigned long long a,
                                                   unsigned long long b,
                                                   unsigned long long c) {
    unsigned long long d;
    asm("fma.rn.f32x2 %0, %1, %2, %3;" : "=l"(d) : "l"(a), "l"(b), "l"(c));
    return d;
}
__device__ __forceinline__ float lo32(unsigned long long u) {
    return __int_as_float((int)(unsigned)(u & 0xffffffffull));
}
__device__ __forceinline__ float hi32(unsigned long long u) {
    return __int_as_float((int)(unsigned)(u >> 32));
}

// ---------------- setup kernels ----------------
__global__ void k_init() {
    int i = blockIdx.x * blockDim.x + threadIdx.x;
    if (i < NPTS) { g_w1[i] = -1; g_w2[i] = -1; }
    if (i < BB)   g_vols[i] = 0.f;
    if (i == 0)   g_volc = 0.f;
}

__global__ void k_winners(const int* __restrict__ idx1, const int* __restrict__ idx2) {
    int i = blockIdx.x * blockDim.x + threadIdx.x;
    if (i < NMOV) atomicMax(&g_w1[idx1[i]], i);
    if (i < NBND) atomicMax(&g_w2[idx2[i]], i);
}

__global__ void k_pz(const float* __restrict__ x, const float* __restrict__ y,
                     const float* __restrict__ p0) {
    int i = blockIdx.x * blockDim.x + threadIdx.x;
    if (i >= BB * NPTS) return;
    int b = i / NPTS, p = i - b * NPTS;
    float vx = p0[p * 3 + 0], vy = p0[p * 3 + 1], vz = p0[p * 3 + 2];
    int w2 = g_w2[p];
    if (w2 >= 0) {
        vx = y[b * 2 * NBND + 2 * w2 + 0];
        vz = y[b * 2 * NBND + 2 * w2 + 1];
    }
    int w1 = g_w1[p];
    if (w1 >= 0) {
        const float* xr = x + (size_t)(b * NMOV + w1) * 3;
        vx = xr[0]; vy = xr[1]; vz = xr[2];
    }
    float* o = g_pz + (size_t)(b * NPTS + p) * 3;
    o[0] = vx; o[1] = vy; o[2] = vz;
}

__global__ void k_copy(const float* __restrict__ x, float* __restrict__ out) {
    int i = blockIdx.x * blockDim.x + threadIdx.x;
    if (i < BB * NMOV * 3) out[i] = x[i];
}

__global__ void k_volc(const float* __restrict__ p0, const int* __restrict__ tri) {
    int t = blockIdx.x * blockDim.x + threadIdx.x;
    float term = 0.f;
    if (t < NTRI) {
        int i0 = tri[t * 3 + 0], i1 = tri[t * 3 + 1], i2 = tri[t * 3 + 2];
        float x0 = p0[i0 * 3], y0 = p0[i0 * 3 + 1], z0 = p0[i0 * 3 + 2];
        float x1 = p0[i1 * 3], y1 = p0[i1 * 3 + 1], z1 = p0[i1 * 3 + 2];
        float x2 = p0[i2 * 3], y2 = p0[i2 * 3 + 1], z2 = p0[i2 * 3 + 2];
        float d = ((y1 - y0) * (z2 - z0) - (z1 - z0) * (y2 - y0)) * (1.f / 6.f);
        term = (x0 + x1 + x2) * d;
    }
    #pragma unroll
    for (int off = 16; off; off >>= 1) term += __shfl_xor_sync(0xffffffffu, term, off);
    __shared__ float ws[8];
    int lane = threadIdx.x & 31, warp = threadIdx.x >> 5;
    if (lane == 0) ws[warp] = term;
    __syncthreads();
    if (threadIdx.x == 0) {
        float s = 0.f;
        #pragma unroll
        for (int w = 0; w < 8; w++) s += ws[w];
        atomicAdd(&g_volc, s);
    }
}

__global__ void k_vols(const int* __restrict__ tri) {
    __shared__ float sacc[BB];
    if (threadIdx.x < BB) sacc[threadIdx.x] = 0.f;
    __syncthreads();
    int i = blockIdx.x * blockDim.x + threadIdx.x;
    if (i < NTRI * BB) {
        int t = i >> 4, b = i & 15;
        int i0 = tri[t * 3 + 0], i1 = tri[t * 3 + 1], i2 = tri[t * 3 + 2];
        const float* P = g_pz + (size_t)b * NPTS * 3;
        float x0 = P[i0 * 3], y0 = P[i0 * 3 + 1], z0 = P[i0 * 3 + 2];
        float x1 = P[i1 * 3], y1 = P[i1 * 3 + 1], z1 = P[i1 * 3 + 2];
        float x2 = P[i2 * 3], y2 = P[i2 * 3 + 1], z2 = P[i2 * 3 + 2];
        float d = ((y1 - y0) * (z2 - z0) - (z1 - z0) * (y2 - y0)) * (1.f / 6.f);
        atomicAdd(&sacc[b], (x0 + x1 + x2) * d);
    }
    __syncthreads();
    if (threadIdx.x < BB) atomicAdd(&g_vols[threadIdx.x], sacc[threadIdx.x]);
}

__global__ void k_a() {
    int b = threadIdx.x;
    if (b < BB) g_a[b] = (g_volc - g_vols[b]) * (1.f / 3.f);
}

// ---------------- per-axis: triangle coefficients into pair-planes ----------------
__global__ void k_D(const int* __restrict__ tri, int axis) {
    int i = blockIdx.x * blockDim.x + threadIdx.x;
    if (blockIdx.x == 0 && threadIdx.x < BB) g_ssq[threadIdx.x] = 0.f;
    if (i >= NTRI * BB) return;
    int b = i / NTRI, t = i - b * NTRI;      // b slow -> coalesced plane writes
    int i0 = tri[t * 3 + 0], i1 = tri[t * 3 + 1], i2 = tri[t * 3 + 2];
    const float* P = g_pz + (size_t)b * NPTS * 3;
    float d;
    if (axis == 2) {
        float x0 = P[i0 * 3], y0 = P[i0 * 3 + 1];
        float x1 = P[i1 * 3], y1 = P[i1 * 3 + 1];
        float x2 = P[i2 * 3], y2 = P[i2 * 3 + 1];
        d = ((x0 - x2) * (y1 - y2) - (y0 - y2) * (x1 - x2)) * (1.f / 6.f);
    } else if (axis == 1) {
        float x0 = P[i0 * 3], z0 = P[i0 * 3 + 2];
        float x1 = P[i1 * 3], z1 = P[i1 * 3 + 2];
        float x2 = P[i2 * 3], z2 = P[i2 * 3 + 2];
        d = ((x0 - x1) * (z2 - z1) - (z0 - z1) * (x2 - x1)) * (1.f / 6.f);
    } else {
        float y0 = P[i0 * 3 + 1], z0 = P[i0 * 3 + 2];
        float y1 = P[i1 * 3 + 1], z1 = P[i1 * 3 + 2];
        float y2 = P[i2 * 3 + 1], z2 = P[i2 * 3 + 2];
        d = ((y1 - y0) * (z2 - z0) - (z1 - z0) * (y2 - y0)) * (1.f / 6.f);
    }
    // plane p = b>>1, half = b&1 : float index (p*NTRI + t)*2 + half
    ((float*)g_Dp)[(((size_t)(b >> 1) * NTRI + t) << 1) + (b & 1)] = d;
}

// ---------------- cp.async helpers ----------------
__device__ __forceinline__ void cp16(unsigned smem_addr, const void* gptr) {
    asm volatile("cp.async.cg.shared.global [%0], [%1], 16;"
                 :: "r"(smem_addr), "l"(gptr));
}
__device__ __forceinline__ void cp_commit() { asm volatile("cp.async.commit_group;"); }
__device__ __forceinline__ void cp_wait1()  { asm volatile("cp.async.wait_group 1;"); }
__device__ __forceinline__ void cp_wait0()  { asm volatile("cp.async.wait_group 0;"); }

// ---------------- skinny GEMM: C[m][b] = sum_t Vf[m][t] * D[t][b] ----------------
// 128 threads = 4 warps, each warp owns 4 m-rows -> 16 rows/block -> 250 blocks.
// D staged via cp.async double buffer as 8 pair-planes [p][KC] of float2:
// lanes read consecutive t -> conflict-free LDS.64 (2-wavefront minimum).
// Vf: stride-1-lane scalar __ldcs loads, register double-buffered GJ=5 groups.
__global__ __launch_bounds__(128) void k_gemm(const float* __restrict__ Vf) {
    __shared__ unsigned long long Ds[2 * 8 * KC];
    const int tid = threadIdx.x;
    const int warp = tid >> 5, lane = tid & 31;
    const int row0 = blockIdx.x * 16 + warp * 4;

    const unsigned smem_base = (unsigned)__cvta_generic_to_shared(Ds);

    // stage one chunk (8 planes x KC pairs = 20KB) into buffer buf
    auto stage = [&](int chunk, int buf) {
        const char* gbase = (const char*)g_Dp;
        unsigned sbase = smem_base + (unsigned)buf * (8 * KC * 8);
        #pragma unroll
        for (int i = 0; i < (8 * KC / 2) / 128; i++) {      // 1280 16B chunks / 128 thr
            int idx = tid + i * 128;
            int p = idx / (KC / 2);
            int off = idx - p * (KC / 2);
            cp16(sbase + (unsigned)(p * KC + off * 2) * 8,
                 gbase + ((size_t)p * NTRI + (size_t)chunk * KC) * 8 + (size_t)off * 16);
        }
        cp_commit();
    };

    unsigned long long acc[4][8];
    #pragma unroll
    for (int r = 0; r < 4; r++)
        #pragma unroll
        for (int p = 0; p < 8; p++) acc[r][p] = 0ull;

    stage(0, 0);

    const float* vrow[4];
    #pragma unroll
    for (int r = 0; r < 4; r++) vrow[r] = Vf + (size_t)(row0 + r) * NTRI + lane;

    // prefetch first Vf group
    float va[4][GJ], vb[4][GJ];
    #pragma unroll
    for (int j = 0; j < GJ; j++)
        #pragma unroll
        for (int r = 0; r < 4; r++) va[r][j] = __ldcs(vrow[r] + 32 * j);

    for (int c = 0; c < NCHUNK; c++) {
        int buf = c & 1;
        if (c + 1 < NCHUNK) { stage(c + 1, buf ^ 1); cp_wait1(); }
        else                { cp_wait0(); }
        __syncthreads();

        const unsigned long long* dsb = Ds + (size_t)buf * 8 * KC;
        #pragma unroll
        for (int g = 0; g < KC / 32 / GJ; g++) {            // 2 groups of GJ=5 jj
            int jj0 = g * GJ;
            // prefetch next group (next g, or first group of next chunk)
            bool last_g = (g == KC / 32 / GJ - 1);
            int nbase = last_g ? ((c + 1) * KC) : (c * KC + (jj0 + GJ) * 32);
            if (c + 1 < NCHUNK || !last_g) {
                #pragma unroll
                for (int j = 0; j < GJ; j++)
                    #pragma unroll
                    for (int r = 0; r < 4; r++)
                        vb[r][j] = __ldcs(vrow[r] + nbase + 32 * j);
            }
            #pragma unroll
            for (int j = 0; j < GJ; j++) {
                const unsigned long long* dp = dsb + (jj0 + j) * 32 + lane;
                unsigned long long dv[8];
                #pragma unroll
                for (int p = 0; p < 8; p++) dv[p] = dp[(size_t)p * KC];
                #pragma unroll
                for (int r = 0; r < 4; r++) {
                    unsigned long long s = splat2(va[r][j]);
                    #pragma unroll
                    for (int p = 0; p < 8; p++) acc[r][p] = fma2(s, dv[p], acc[r][p]);
                }
            }
            #pragma unroll
            for (int j = 0; j < GJ; j++)
                #pragma unroll
                for (int r = 0; r < 4; r++) va[r][j] = vb[r][j];
        }
        __syncthreads();
    }

    // reduce across the 32 t-lanes
    #pragma unroll
    for (int r = 0; r < 4; r++)
        #pragma unroll
        for (int p = 0; p < 8; p++) {
            float l = lo32(acc[r][p]), h = hi32(acc[r][p]);
            #pragma unroll
            for (int off = 16; off; off >>= 1) {
                l += __shfl_xor_sync(0xffffffffu, l, off);
                h += __shfl_xor_sync(0xffffffffu, h, off);
            }
            asm("mov.b64 %0, {%1, %2};" : "=l"(acc[r][p])
                : "r"(__float_as_uint(l)), "r"(__float_as_uint(h)));
        }

    if (lane == 0) {
        float sq[BB];
        #pragma unroll
        for (int b = 0; b < BB; b++) sq[b] = 0.f;
        #pragma unroll
        for (int r = 0; r < 4; r++) {
            unsigned long long* crow = (unsigned long long*)(g_C + (size_t)(row0 + r) * BB);
            #pragma unroll
            for (int p = 0; p < 8; p++) {
                crow[p] = acc[r][p];
                float l = lo32(acc[r][p]), h = hi32(acc[r][p]);
                sq[2 * p]     += l * l;
                sq[2 * p + 1] += h * h;
            }
        }
        #pragma unroll
        for (int b = 0; b < BB; b++) atomicAdd(&g_ssq[b], sq[b]);
    }
}

// ---------------- per-axis: solve + update pts + maintain pz ----------------
__global__ void k_update(const int* __restrict__ idx1, float* __restrict__ out, int axis) {
    int i = blockIdx.x * blockDim.x + threadIdx.x;
    if (i >= NMOV * BB) return;
    int m = i % NMOV, b = i / NMOV;
    float c = g_C[(size_t)m * BB + b];
    float s = g_a[b] / (g_ssq[b] + EPSV);
    size_t o = (size_t)(b * NMOV + m) * 3 + axis;
    float nv = out[o] + c * s;
    out[o] = nv;
    int p = idx1[m];
    if (g_w1[p] == m) g_pz[(size_t)(b * NPTS + p) * 3 + axis] = nv;
}

// ---------------- launch ----------------
extern "C" void kernel_launch(void* const* d_in, const int* in_sizes, int n_in,
                              void* d_out, int out_size) {
    const float* x   = (const float*)d_in[0];
    const float* y   = (const float*)d_in[1];
    const float* p0  = (const float*)d_in[2];
    const float* Vf  = (const float*)d_in[3];
    const int* idx1  = (const int*)d_in[4];
    const int* idx2  = (const int*)d_in[5];
    const int* tri   = (const int*)d_in[6];
    float* out       = (float*)d_out;

    k_init   <<<(NPTS + 255) / 256, 256>>>();
    k_winners<<<(NMOV + 255) / 256, 256>>>(idx1, idx2);
    k_pz     <<<(BB * NPTS + 255) / 256, 256>>>(x, y, p0);
    k_copy   <<<(BB * NMOV * 3 + 255) / 256, 256>>>(x, out);
    k_volc   <<<(NTRI + 255) / 256, 256>>>(p0, tri);
    k_vols   <<<(NTRI * BB + 255) / 256, 256>>>(tri);
    k_a      <<<1, 32>>>();

    const int axes[3] = {2, 1, 0};
    for (int ai = 0; ai < 3; ai++) {
        int axis = axes[ai];
        k_D     <<<(NTRI * BB + 255) / 256, 256>>>(tri, axis);
        k_gemm  <<<NMOV / 16, 128>>>(Vf);
        k_update<<<(NMOV * BB + 255) / 256, 256>>>(idx1, out, axis);
    }
}